// round 14
// baseline (speedup 1.0000x reference)
#include <cuda_runtime.h>
#include <cuda_fp16.h>
#include <cstdint>

#define DM   2048
#define HID  5461
#define HPAD 5504
#define MTOT 16384

// ---------------- scratch (device globals; no allocations) ----------------
__device__ __align__(256) __half g_xh [(size_t)MTOT * DM];   // x in fp16
__device__ __align__(256) __half g_w1q[(size_t)HPAD * DM];   // ternary {-1,0,1} fp16
__device__ __align__(256) __half g_w3q[(size_t)HPAD * DM];
__device__ __align__(256) __half g_w2q[(size_t)DM * HPAD];   // [d][h] padded cols zero
__device__ __align__(256) __half g_act[(size_t)MTOT * HPAD]; // gated activation fp16
__device__ float g_partial[3 * 512];
__device__ float g_scale[3];                                  // s1, s3, s2

// ---------------- prologue kernels ----------------
__global__ void reduce_abs3_k(const float* __restrict__ w1, const float* __restrict__ w3,
                              const float* __restrict__ w2, int n4) {
    __shared__ float sd[256];
    const float* w = (blockIdx.y == 0) ? w1 : (blockIdx.y == 1) ? w3 : w2;
    const float4* w4 = (const float4*)w;
    float s = 0.f;
    for (int i = blockIdx.x * blockDim.x + threadIdx.x; i < n4; i += gridDim.x * blockDim.x) {
        float4 v = w4[i];
        s += fabsf(v.x) + fabsf(v.y) + fabsf(v.z) + fabsf(v.w);
    }
    sd[threadIdx.x] = s; __syncthreads();
    for (int st = 128; st > 0; st >>= 1) {
        if (threadIdx.x < st) sd[threadIdx.x] += sd[threadIdx.x + st];
        __syncthreads();
    }
    if (threadIdx.x == 0) g_partial[blockIdx.y * 512 + blockIdx.x] = sd[0];
}

// conv_x with finalize folded into blocks 0..2 (same pairwise tree as the old
// finalize3_k -> bitwise-identical g_scale).
__global__ void convx_fin_k(const float* __restrict__ x) {
    __shared__ float sd[256];
    if (blockIdx.x < 3) {
        const int z = blockIdx.x, tid = threadIdx.x;
        sd[tid] = g_partial[z * 512 + tid] + g_partial[z * 512 + 256 + tid];
        __syncthreads();
        for (int st = 128; st > 0; st >>= 1) {
            if (tid < st) sd[tid] += sd[tid + st];
            __syncthreads();
        }
        if (tid == 0) g_scale[z] = sd[0] / (float)(HID * DM);
    }
    int i = blockIdx.x * blockDim.x + threadIdx.x;
    const int n4 = MTOT * DM / 4;
    if (i >= n4) return;
    float4 v = ((const float4*)x)[i];
    ((__half2*)g_xh)[2 * i]     = __floats2half2_rn(v.x, v.y);
    ((__half2*)g_xh)[2 * i + 1] = __floats2half2_rn(v.z, v.w);
}

__device__ __forceinline__ float tq(float w, float s) {
    float t = rintf(w / s);                      // round-half-even, matches jnp.round
    return fmaxf(-1.f, fminf(1.f, t));
}

// Fused weight quantization. grid (2, HPAD, 3), 256 threads.
__global__ void quant_all_k(const float* __restrict__ w1, const float* __restrict__ w3,
                            const float* __restrict__ w2) {
    const int z = blockIdx.z;
    if (z < 2) {
        const float* w = z ? w3 : w1;
        __half* q = z ? g_w3q : g_w1q;
        const int r = blockIdx.y;
        const int c = (blockIdx.x * blockDim.x + threadIdx.x) << 2;
        __half2 h0, h1;
        if (r < HID) {
            const float s = g_scale[z];
            float4 v = *(const float4*)(w + (size_t)r * DM + c);
            h0 = __floats2half2_rn(tq(v.x, s), tq(v.y, s));
            h1 = __floats2half2_rn(tq(v.z, s), tq(v.w, s));
        } else {
            h0 = __floats2half2_rn(0.f, 0.f);
            h1 = h0;
        }
        uint2 pack;
        pack.x = *(unsigned*)&h0;
        pack.y = *(unsigned*)&h1;
        *(uint2*)(q + (size_t)r * DM + c) = pack;
    } else {
        const int d = blockIdx.y;
        if (d >= DM) return;
        const float s = g_scale[2];
        const float* row = w2 + (size_t)d * HID;
#pragma unroll
        for (int j = 0; j < 3; j++) {
            const int h = (blockIdx.x * blockDim.x + threadIdx.x + j * 512) << 2;
            if (h >= HPAD) break;
            float v[4];
#pragma unroll
            for (int k = 0; k < 4; k++) {
                int hk = h + k;
                v[k] = (hk < HID) ? tq(row[hk], s) : 0.f;
            }
            __half2 h0 = __floats2half2_rn(v[0], v[1]);
            __half2 h1 = __floats2half2_rn(v[2], v[3]);
            uint2 pack;
            pack.x = *(unsigned*)&h0;
            pack.y = *(unsigned*)&h1;
            *(uint2*)(g_w2q + (size_t)d * HPAD + h) = pack;
        }
    }
}

// ---------------- GEMM building blocks ----------------
#define CP_ASYNC16(s, g) asm volatile("cp.async.cg.shared.global [%0], [%1], 16;\n" :: "r"(s), "l"(g))
#define CP_COMMIT()      asm volatile("cp.async.commit_group;\n" ::)
#define CP_WAIT(N)       asm volatile("cp.async.wait_group %0;\n" :: "n"(N))

__device__ __forceinline__ unsigned sptr(const void* p) {
    return (unsigned)__cvta_generic_to_shared(p);
}

__device__ __forceinline__ void ldsm4(unsigned& r0, unsigned& r1, unsigned& r2, unsigned& r3, unsigned a) {
    asm volatile("ldmatrix.sync.aligned.m8n8.x4.shared.b16 {%0,%1,%2,%3}, [%4];\n"
                 : "=r"(r0), "=r"(r1), "=r"(r2), "=r"(r3) : "r"(a));
}

__device__ __forceinline__ void mma16816(float* c, const unsigned* a, unsigned b0, unsigned b1) {
    asm volatile(
        "mma.sync.aligned.m16n8k16.row.col.f32.f16.f16.f32 "
        "{%0,%1,%2,%3},{%4,%5,%6,%7},{%8,%9},{%0,%1,%2,%3};\n"
        : "+f"(c[0]), "+f"(c[1]), "+f"(c[2]), "+f"(c[3])
        : "r"(a[0]), "r"(a[1]), "r"(a[2]), "r"(a[3]), "r"(b0), "r"(b1));
}

// 128B-row swizzle: row = 64 halves, 8 chunks of 16B, chunk XOR (row&7). Offsets in halves.
__device__ __forceinline__ int swz(int row, int ch) {
    return (row << 6) + (((ch ^ row) & 7) << 3);
}

__device__ __forceinline__ float siluf(float x) { return x / (1.f + __expf(-x)); }

// One BK=64 panel of MMAs, dual-B (w1 and w3 share the A fragments).
// Warp tile 64(M) x 32(N); wm selects 64-row block, wn selects 32-col block.
__device__ __forceinline__ void mma_stage_dual(
    const __half* As, const __half* B1s, const __half* B3s,
    int lane, int wm, int wn, float acc1[4][4][4], float acc3[4][4][4])
{
#pragma unroll
    for (int kk = 0; kk < 4; kk++) {
        unsigned a[4][4];
#pragma unroll
        for (int mi = 0; mi < 4; mi++) {
            int row = (wm << 6) + (mi << 4) + (lane & 15);
            int ch  = (kk << 1) + (lane >> 4);
            ldsm4(a[mi][0], a[mi][1], a[mi][2], a[mi][3], sptr(As + swz(row, ch)));
        }
        unsigned b1[2][4], b3[2][4];
#pragma unroll
        for (int gi = 0; gi < 2; gi++) {
            int mat = lane >> 3;
            int row = (wn << 5) + (gi << 4) + ((mat >> 1) << 3) + (lane & 7);
            int ch  = (kk << 1) + (mat & 1);
            ldsm4(b1[gi][0], b1[gi][1], b1[gi][2], b1[gi][3], sptr(B1s + swz(row, ch)));
            ldsm4(b3[gi][0], b3[gi][1], b3[gi][2], b3[gi][3], sptr(B3s + swz(row, ch)));
        }
#pragma unroll
        for (int mi = 0; mi < 4; mi++) {
#pragma unroll
            for (int ni = 0; ni < 4; ni++) {
                int gi = ni >> 1, p = (ni & 1) << 1;
                mma16816(acc1[mi][ni], a[mi], b1[gi][p], b1[gi][p + 1]);
                mma16816(acc3[mi][ni], a[mi], b3[gi][p], b3[gi][p + 1]);
            }
        }
    }
}

// One BK=64 panel of MMAs, single B. Warp tile 64(M) x 32(N).
__device__ __forceinline__ void mma_stage_single(
    const __half* As, const __half* Bs,
    int lane, int wm, int wn, float acc[4][4][4])
{
#pragma unroll
    for (int kk = 0; kk < 4; kk++) {
        unsigned a[4][4];
#pragma unroll
        for (int mi = 0; mi < 4; mi++) {
            int row = (wm << 6) + (mi << 4) + (lane & 15);
            int ch  = (kk << 1) + (lane >> 4);
            ldsm4(a[mi][0], a[mi][1], a[mi][2], a[mi][3], sptr(As + swz(row, ch)));
        }
        unsigned b[2][4];
#pragma unroll
        for (int gi = 0; gi < 2; gi++) {
            int mat = lane >> 3;
            int row = (wn << 5) + (gi << 4) + ((mat >> 1) << 3) + (lane & 7);
            int ch  = (kk << 1) + (mat & 1);
            ldsm4(b[gi][0], b[gi][1], b[gi][2], b[gi][3], sptr(Bs + swz(row, ch)));
        }
#pragma unroll
        for (int mi = 0; mi < 4; mi++) {
#pragma unroll
            for (int ni = 0; ni < 4; ni++) {
                int gi = ni >> 1, p = (ni & 1) << 1;
                mma16816(acc[mi][ni], a[mi], b[gi][p], b[gi][p + 1]);
            }
        }
    }
}

// ---------------- GEMM1 (fused h1/h3 + SiLU gate) ----------------
// C tile 128(M) x 64(N of both h1,h3), K=2048, BK=64, 3-stage pipeline,
// 128 threads (4 warps: wm in {0,1}, wn in {0,1}), 96KB smem -> 2 CTAs/SM.
// Stage layout (halves): A [0,8192) | B1 [8192,12288) | B3 [12288,16384)
#define G1_STG 16384
#define G1_SMEM (3 * G1_STG * 2)

__device__ __forceinline__ void g1_load(__half* st, const __half* gA, const __half* gB1,
                                        const __half* gB3, int k0, int lrow, int lch) {
#pragma unroll
    for (int i = 0; i < 8; i++) {       // A: 128 rows
        int row = lrow + (i << 4);
        int so = swz(row, lch);
        CP_ASYNC16(sptr(st + so), gA + (size_t)row * DM + k0 + lch * 8);
    }
#pragma unroll
    for (int i = 0; i < 4; i++) {       // B1/B3: 64 rows each
        int row = lrow + (i << 4);
        int so = swz(row, lch);
        size_t go = (size_t)row * DM + k0 + lch * 8;
        CP_ASYNC16(sptr(st + 8192 + so),  gB1 + go);
        CP_ASYNC16(sptr(st + 12288 + so), gB3 + go);
    }
}

__global__ __launch_bounds__(128, 2) void gemm1_k() {
    extern __shared__ __align__(16) __half sm1[];

    const int tid = threadIdx.x, lane = tid & 31, w = tid >> 5;
    const int wm = w >> 1, wn = w & 1;
    const int bm = blockIdx.y, bn = blockIdx.x;
    const int lrow = tid >> 3, lch = tid & 7;   // 16 rows per pass, 8 chunks/row

    const __half* gA  = g_xh  + (size_t)bm * 128 * DM;
    const __half* gB1 = g_w1q + (size_t)bn * 64 * DM;
    const __half* gB3 = g_w3q + (size_t)bn * 64 * DM;

    float acc1[4][4][4], acc3[4][4][4];
#pragma unroll
    for (int i = 0; i < 4; i++)
#pragma unroll
        for (int j = 0; j < 4; j++)
#pragma unroll
            for (int k = 0; k < 4; k++) { acc1[i][j][k] = 0.f; acc3[i][j][k] = 0.f; }

    const int KT = DM / 64;  // 32

    // prologue: fill stages 0,1
#pragma unroll
    for (int s = 0; s < 2; s++) {
        g1_load(sm1 + s * G1_STG, gA, gB1, gB3, s * 64, lrow, lch);
        CP_COMMIT();
    }

    int stg_w = 2, stg_r = 0;   // write/read stage indices (mod 3)
    for (int kt = 0; kt < KT; kt++) {
        CP_WAIT(1);               // stage kt landed (this thread's copies)
        __syncthreads();          // ...and everyone's copies visible
        const int nx = kt + 2;
        if (nx < KT)
            g1_load(sm1 + stg_w * G1_STG, gA, gB1, gB3, nx * 64, lrow, lch);
        CP_COMMIT();
        const __half* stb = sm1 + stg_r * G1_STG;
        mma_stage_dual(stb, stb + 8192, stb + 12288, lane, wm, wn, acc1, acc3);
        stg_w = (stg_w == 2) ? 0 : stg_w + 1;
        stg_r = (stg_r == 2) ? 0 : stg_r + 1;
    }

    // epilogue: g = silu(s1*h1) * (s3*h3), fp16 store
    const float s1 = g_scale[0], s3v = g_scale[1];
    const int rb = bm * 128 + wm * 64;
    const int cb = bn * 64 + wn * 32;
#pragma unroll
    for (int mi = 0; mi < 4; mi++) {
        int r0 = rb + mi * 16 + (lane >> 2);
#pragma unroll
        for (int ni = 0; ni < 4; ni++) {
            int c = cb + ni * 8 + ((lane & 3) << 1);
            float h10 = s1 * acc1[mi][ni][0], h11 = s1 * acc1[mi][ni][1];
            float h12 = s1 * acc1[mi][ni][2], h13 = s1 * acc1[mi][ni][3];
            float h30 = s3v * acc3[mi][ni][0], h31 = s3v * acc3[mi][ni][1];
            float h32 = s3v * acc3[mi][ni][2], h33 = s3v * acc3[mi][ni][3];
            float g0 = siluf(h10) * h30, g1 = siluf(h11) * h31;
            float g2 = siluf(h12) * h32, g3 = siluf(h13) * h33;
            *(__half2*)(g_act + (size_t)r0 * HPAD + c)       = __floats2half2_rn(g0, g1);
            *(__half2*)(g_act + (size_t)(r0 + 8) * HPAD + c) = __floats2half2_rn(g2, g3);
        }
    }
}

// ---------------- GEMM2: out = s2 * (g . w2q^T) ----------------
// C tile 128(M) x 64(N), K=HPAD, BK=64, 4-stage pipeline (depth-3 prefetch),
// 128 threads (4 warps), 96KB smem -> 2 CTAs/SM.
// Stage layout (halves): A [0,8192) | B [8192,12288)
#define G2_STG 12288
#define G2_SMEM (4 * G2_STG * 2)

__device__ __forceinline__ void g2_load(__half* st, const __half* gA, const __half* gB,
                                        int k0, int lrow, int lch) {
#pragma unroll
    for (int i = 0; i < 8; i++) {       // A: 128 rows
        int row = lrow + (i << 4);
        int so = swz(row, lch);
        CP_ASYNC16(sptr(st + so), gA + (size_t)row * HPAD + k0 + lch * 8);
    }
#pragma unroll
    for (int i = 0; i < 4; i++) {       // B: 64 rows
        int row = lrow + (i << 4);
        int so = swz(row, lch);
        CP_ASYNC16(sptr(st + 8192 + so), gB + (size_t)row * HPAD + k0 + lch * 8);
    }
}

__global__ __launch_bounds__(128, 2) void gemm2_k(float* __restrict__ out) {
    extern __shared__ __align__(16) __half sm2[];

    const int tid = threadIdx.x, lane = tid & 31, w = tid >> 5;
    const int wm = w >> 1, wn = w & 1;
    const int bm = blockIdx.y, bn = blockIdx.x;
    const int lrow = tid >> 3, lch = tid & 7;

    const __half* gA = g_act + (size_t)bm * 128 * HPAD;
    const __half* gB = g_w2q + (size_t)bn * 64 * HPAD;

    float acc[4][4][4];
#pragma unroll
    for (int i = 0; i < 4; i++)
#pragma unroll
        for (int j = 0; j < 4; j++)
#pragma unroll
            for (int k = 0; k < 4; k++) acc[i][j][k] = 0.f;

    const int KT = HPAD / 64;  // 86

    // prologue: fill stages 0..2
#pragma unroll
    for (int s = 0; s < 3; s++) {
        g2_load(sm2 + s * G2_STG, gA, gB, s * 64, lrow, lch);
        CP_COMMIT();
    }

    for (int kt = 0; kt < KT; kt++) {
        CP_WAIT(2);               // stage kt landed (this thread's copies)
        __syncthreads();          // ...and everyone's copies visible
        const int nx = kt + 3;
        if (nx < KT)
            g2_load(sm2 + ((kt + 3) & 3) * G2_STG, gA, gB, nx * 64, lrow, lch);
        CP_COMMIT();
        const __half* stb = sm2 + (kt & 3) * G2_STG;
        mma_stage_single(stb, stb + 8192, lane, wm, wn, acc);
    }

    const float s2 = g_scale[2];
    const int rb = bm * 128 + wm * 64;
    const int cb = bn * 64 + wn * 32;
#pragma unroll
    for (int mi = 0; mi < 4; mi++) {
        int r0 = rb + mi * 16 + (lane >> 2);
#pragma unroll
        for (int ni = 0; ni < 4; ni++) {
            int c = cb + ni * 8 + ((lane & 3) << 1);
            float2 v;
            v.x = s2 * acc[mi][ni][0]; v.y = s2 * acc[mi][ni][1];
            *(float2*)(out + (size_t)r0 * DM + c) = v;
            v.x = s2 * acc[mi][ni][2]; v.y = s2 * acc[mi][ni][3];
            *(float2*)(out + (size_t)(r0 + 8) * DM + c) = v;
        }
    }
}

// ---------------- launch ----------------
extern "C" void kernel_launch(void* const* d_in, const int* in_sizes, int n_in,
                              void* d_out, int out_size) {
    const float* x  = (const float*)d_in[0];
    const float* w1 = (const float*)d_in[1];
    const float* w3 = (const float*)d_in[2];
    const float* w2 = (const float*)d_in[3];
    float* out = (float*)d_out;

    const int nw = HID * DM;  // 11,184,128 (divisible by 4)

    cudaFuncSetAttribute(gemm1_k, cudaFuncAttributeMaxDynamicSharedMemorySize, G1_SMEM);
    cudaFuncSetAttribute(gemm2_k, cudaFuncAttributeMaxDynamicSharedMemorySize, G2_SMEM);

    reduce_abs3_k<<<dim3(512, 3), 256>>>(w1, w3, w2, nw / 4);             // 1
    convx_fin_k<<<MTOT * DM / 4 / 256, 256>>>(x);                         // 2
    quant_all_k<<<dim3(2, HPAD, 3), 256>>>(w1, w3, w2);                   // 3
    gemm1_k<<<dim3(HPAD / 64, MTOT / 128), 128, G1_SMEM>>>();             // 4 <- profiled
    gemm2_k<<<dim3(DM / 64, MTOT / 128), 128, G2_SMEM>>>(out);            // 5
}

// round 15
// speedup vs baseline: 1.0436x; 1.0436x over previous
#include <cuda_runtime.h>
#include <cuda_fp16.h>
#include <cstdint>

#define DM   2048
#define HID  5461
#define HPAD 5504
#define MTOT 16384

// ---------------- scratch (device globals; no allocations) ----------------
__device__ __align__(256) __half g_xh [(size_t)MTOT * DM];   // x in fp16
__device__ __align__(256) __half g_w1q[(size_t)HPAD * DM];   // ternary {-1,0,1} fp16
__device__ __align__(256) __half g_w3q[(size_t)HPAD * DM];
__device__ __align__(256) __half g_w2q[(size_t)DM * HPAD];   // [d][h] padded cols zero
__device__ __align__(256) __half g_act[(size_t)MTOT * HPAD]; // gated activation fp16
__device__ float g_partial[3 * 512];
__device__ float g_scale[3];                                  // s1, s3, s2

// ---------------- prologue kernels ----------------
__global__ void reduce_abs3_k(const float* __restrict__ w1, const float* __restrict__ w3,
                              const float* __restrict__ w2, int n4) {
    __shared__ float sd[256];
    const float* w = (blockIdx.y == 0) ? w1 : (blockIdx.y == 1) ? w3 : w2;
    const float4* w4 = (const float4*)w;
    float s = 0.f;
    for (int i = blockIdx.x * blockDim.x + threadIdx.x; i < n4; i += gridDim.x * blockDim.x) {
        float4 v = w4[i];
        s += fabsf(v.x) + fabsf(v.y) + fabsf(v.z) + fabsf(v.w);
    }
    sd[threadIdx.x] = s; __syncthreads();
    for (int st = 128; st > 0; st >>= 1) {
        if (threadIdx.x < st) sd[threadIdx.x] += sd[threadIdx.x + st];
        __syncthreads();
    }
    if (threadIdx.x == 0) g_partial[blockIdx.y * 512 + blockIdx.x] = sd[0];
}

// conv_x with finalize folded into blocks 0..2 (same pairwise tree as the old
// finalize3_k -> bitwise-identical g_scale).
__global__ void convx_fin_k(const float* __restrict__ x) {
    __shared__ float sd[256];
    if (blockIdx.x < 3) {
        const int z = blockIdx.x, tid = threadIdx.x;
        sd[tid] = g_partial[z * 512 + tid] + g_partial[z * 512 + 256 + tid];
        __syncthreads();
        for (int st = 128; st > 0; st >>= 1) {
            if (tid < st) sd[tid] += sd[tid + st];
            __syncthreads();
        }
        if (tid == 0) g_scale[z] = sd[0] / (float)(HID * DM);
    }
    int i = blockIdx.x * blockDim.x + threadIdx.x;
    const int n4 = MTOT * DM / 4;
    if (i >= n4) return;
    float4 v = ((const float4*)x)[i];
    ((__half2*)g_xh)[2 * i]     = __floats2half2_rn(v.x, v.y);
    ((__half2*)g_xh)[2 * i + 1] = __floats2half2_rn(v.z, v.w);
}

__device__ __forceinline__ float tq(float w, float s) {
    float t = rintf(w / s);                      // round-half-even, matches jnp.round
    return fmaxf(-1.f, fminf(1.f, t));
}

// Fused weight quantization. grid (2, HPAD, 3), 256 threads.
__global__ void quant_all_k(const float* __restrict__ w1, const float* __restrict__ w3,
                            const float* __restrict__ w2) {
    const int z = blockIdx.z;
    if (z < 2) {
        const float* w = z ? w3 : w1;
        __half* q = z ? g_w3q : g_w1q;
        const int r = blockIdx.y;
        const int c = (blockIdx.x * blockDim.x + threadIdx.x) << 2;
        __half2 h0, h1;
        if (r < HID) {
            const float s = g_scale[z];
            float4 v = *(const float4*)(w + (size_t)r * DM + c);
            h0 = __floats2half2_rn(tq(v.x, s), tq(v.y, s));
            h1 = __floats2half2_rn(tq(v.z, s), tq(v.w, s));
        } else {
            h0 = __floats2half2_rn(0.f, 0.f);
            h1 = h0;
        }
        uint2 pack;
        pack.x = *(unsigned*)&h0;
        pack.y = *(unsigned*)&h1;
        *(uint2*)(q + (size_t)r * DM + c) = pack;
    } else {
        const int d = blockIdx.y;
        if (d >= DM) return;
        const float s = g_scale[2];
        const float* row = w2 + (size_t)d * HID;
#pragma unroll
        for (int j = 0; j < 3; j++) {
            const int h = (blockIdx.x * blockDim.x + threadIdx.x + j * 512) << 2;
            if (h >= HPAD) break;
            float v[4];
#pragma unroll
            for (int k = 0; k < 4; k++) {
                int hk = h + k;
                v[k] = (hk < HID) ? tq(row[hk], s) : 0.f;
            }
            __half2 h0 = __floats2half2_rn(v[0], v[1]);
            __half2 h1 = __floats2half2_rn(v[2], v[3]);
            uint2 pack;
            pack.x = *(unsigned*)&h0;
            pack.y = *(unsigned*)&h1;
            *(uint2*)(g_w2q + (size_t)d * HPAD + h) = pack;
        }
    }
}

// ---------------- GEMM building blocks ----------------
#define CP_ASYNC16(s, g) asm volatile("cp.async.cg.shared.global [%0], [%1], 16;\n" :: "r"(s), "l"(g))
#define CP_COMMIT()      asm volatile("cp.async.commit_group;\n" ::)
#define CP_WAIT(N)       asm volatile("cp.async.wait_group %0;\n" :: "n"(N))

__device__ __forceinline__ unsigned sptr(const void* p) {
    return (unsigned)__cvta_generic_to_shared(p);
}

__device__ __forceinline__ void ldsm4(unsigned& r0, unsigned& r1, unsigned& r2, unsigned& r3, unsigned a) {
    asm volatile("ldmatrix.sync.aligned.m8n8.x4.shared.b16 {%0,%1,%2,%3}, [%4];\n"
                 : "=r"(r0), "=r"(r1), "=r"(r2), "=r"(r3) : "r"(a));
}

__device__ __forceinline__ void mma16816(float* c, const unsigned* a, unsigned b0, unsigned b1) {
    asm volatile(
        "mma.sync.aligned.m16n8k16.row.col.f32.f16.f16.f32 "
        "{%0,%1,%2,%3},{%4,%5,%6,%7},{%8,%9},{%0,%1,%2,%3};\n"
        : "+f"(c[0]), "+f"(c[1]), "+f"(c[2]), "+f"(c[3])
        : "r"(a[0]), "r"(a[1]), "r"(a[2]), "r"(a[3]), "r"(b0), "r"(b1));
}

// 128B-row swizzle: row = 64 halves, 8 chunks of 16B, chunk XOR (row&7). Offsets in halves.
__device__ __forceinline__ int swz(int row, int ch) {
    return (row << 6) + (((ch ^ row) & 7) << 3);
}

__device__ __forceinline__ float siluf(float x) { return x / (1.f + __expf(-x)); }

// One BK=64 panel of MMAs, dual-B (w1 and w3 share the A fragments).
// Warp tile 64(M) x 32(N); wm selects 64-row block, wn selects 32-col block.
__device__ __forceinline__ void mma_stage_dual(
    const __half* As, const __half* B1s, const __half* B3s,
    int lane, int wm, int wn, float acc1[4][4][4], float acc3[4][4][4])
{
#pragma unroll
    for (int kk = 0; kk < 4; kk++) {
        unsigned a[4][4];
#pragma unroll
        for (int mi = 0; mi < 4; mi++) {
            int row = (wm << 6) + (mi << 4) + (lane & 15);
            int ch  = (kk << 1) + (lane >> 4);
            ldsm4(a[mi][0], a[mi][1], a[mi][2], a[mi][3], sptr(As + swz(row, ch)));
        }
        unsigned b1[2][4], b3[2][4];
#pragma unroll
        for (int gi = 0; gi < 2; gi++) {
            int mat = lane >> 3;
            int row = (wn << 5) + (gi << 4) + ((mat >> 1) << 3) + (lane & 7);
            int ch  = (kk << 1) + (mat & 1);
            ldsm4(b1[gi][0], b1[gi][1], b1[gi][2], b1[gi][3], sptr(B1s + swz(row, ch)));
            ldsm4(b3[gi][0], b3[gi][1], b3[gi][2], b3[gi][3], sptr(B3s + swz(row, ch)));
        }
#pragma unroll
        for (int mi = 0; mi < 4; mi++) {
#pragma unroll
            for (int ni = 0; ni < 4; ni++) {
                int gi = ni >> 1, p = (ni & 1) << 1;
                mma16816(acc1[mi][ni], a[mi], b1[gi][p], b1[gi][p + 1]);
                mma16816(acc3[mi][ni], a[mi], b3[gi][p], b3[gi][p + 1]);
            }
        }
    }
}

// One BK=64 panel of MMAs, single B. Warp tile 64(M) x 32(N).
__device__ __forceinline__ void mma_stage_single(
    const __half* As, const __half* Bs,
    int lane, int wm, int wn, float acc[4][4][4])
{
#pragma unroll
    for (int kk = 0; kk < 4; kk++) {
        unsigned a[4][4];
#pragma unroll
        for (int mi = 0; mi < 4; mi++) {
            int row = (wm << 6) + (mi << 4) + (lane & 15);
            int ch  = (kk << 1) + (lane >> 4);
            ldsm4(a[mi][0], a[mi][1], a[mi][2], a[mi][3], sptr(As + swz(row, ch)));
        }
        unsigned b[2][4];
#pragma unroll
        for (int gi = 0; gi < 2; gi++) {
            int mat = lane >> 3;
            int row = (wn << 5) + (gi << 4) + ((mat >> 1) << 3) + (lane & 7);
            int ch  = (kk << 1) + (mat & 1);
            ldsm4(b[gi][0], b[gi][1], b[gi][2], b[gi][3], sptr(Bs + swz(row, ch)));
        }
#pragma unroll
        for (int mi = 0; mi < 4; mi++) {
#pragma unroll
            for (int ni = 0; ni < 4; ni++) {
                int gi = ni >> 1, p = (ni & 1) << 1;
                mma16816(acc[mi][ni], a[mi], b[gi][p], b[gi][p + 1]);
            }
        }
    }
}

// ---------------- GEMM1 (fused h1/h3 + SiLU gate) ----------------
// C tile 128(M) x 64(N of both h1,h3), K=2048, BK=64, 3-stage pipeline,
// 128 threads (4 warps: wm in {0,1}, wn in {0,1}), 96KB smem -> 2 CTAs/SM.
// Stage layout (halves): A [0,8192) | B1 [8192,12288) | B3 [12288,16384)
#define G1_STG 16384
#define G1_SMEM (3 * G1_STG * 2)

__device__ __forceinline__ void g1_load(__half* st, const __half* gA, const __half* gB1,
                                        const __half* gB3, int k0, int lrow, int lch) {
#pragma unroll
    for (int i = 0; i < 8; i++) {       // A: 128 rows
        int row = lrow + (i << 4);
        int so = swz(row, lch);
        CP_ASYNC16(sptr(st + so), gA + (size_t)row * DM + k0 + lch * 8);
    }
#pragma unroll
    for (int i = 0; i < 4; i++) {       // B1/B3: 64 rows each
        int row = lrow + (i << 4);
        int so = swz(row, lch);
        size_t go = (size_t)row * DM + k0 + lch * 8;
        CP_ASYNC16(sptr(st + 8192 + so),  gB1 + go);
        CP_ASYNC16(sptr(st + 12288 + so), gB3 + go);
    }
}

__global__ __launch_bounds__(128, 2) void gemm1_k() {
    extern __shared__ __align__(16) __half sm1[];

    const int tid = threadIdx.x, lane = tid & 31, w = tid >> 5;
    const int wm = w >> 1, wn = w & 1;
    const int bm = blockIdx.y, bn = blockIdx.x;
    const int lrow = tid >> 3, lch = tid & 7;   // 16 rows per pass, 8 chunks/row

    const __half* gA  = g_xh  + (size_t)bm * 128 * DM;
    const __half* gB1 = g_w1q + (size_t)bn * 64 * DM;
    const __half* gB3 = g_w3q + (size_t)bn * 64 * DM;

    float acc1[4][4][4], acc3[4][4][4];
#pragma unroll
    for (int i = 0; i < 4; i++)
#pragma unroll
        for (int j = 0; j < 4; j++)
#pragma unroll
            for (int k = 0; k < 4; k++) { acc1[i][j][k] = 0.f; acc3[i][j][k] = 0.f; }

    const int KT = DM / 64;  // 32

    // prologue: fill stages 0,1
#pragma unroll
    for (int s = 0; s < 2; s++) {
        g1_load(sm1 + s * G1_STG, gA, gB1, gB3, s * 64, lrow, lch);
        CP_COMMIT();
    }

    int stg_w = 2, stg_r = 0;   // write/read stage indices (mod 3)
    for (int kt = 0; kt < KT; kt++) {
        CP_WAIT(1);               // stage kt landed (this thread's copies)
        __syncthreads();          // ...and everyone's copies visible
        const int nx = kt + 2;
        if (nx < KT)
            g1_load(sm1 + stg_w * G1_STG, gA, gB1, gB3, nx * 64, lrow, lch);
        CP_COMMIT();
        const __half* stb = sm1 + stg_r * G1_STG;
        mma_stage_dual(stb, stb + 8192, stb + 12288, lane, wm, wn, acc1, acc3);
        stg_w = (stg_w == 2) ? 0 : stg_w + 1;
        stg_r = (stg_r == 2) ? 0 : stg_r + 1;
    }

    // epilogue: g = silu(s1*h1) * (s3*h3), fp16 store
    const float s1 = g_scale[0], s3v = g_scale[1];
    const int rb = bm * 128 + wm * 64;
    const int cb = bn * 64 + wn * 32;
#pragma unroll
    for (int mi = 0; mi < 4; mi++) {
        int r0 = rb + mi * 16 + (lane >> 2);
#pragma unroll
        for (int ni = 0; ni < 4; ni++) {
            int c = cb + ni * 8 + ((lane & 3) << 1);
            float h10 = s1 * acc1[mi][ni][0], h11 = s1 * acc1[mi][ni][1];
            float h12 = s1 * acc1[mi][ni][2], h13 = s1 * acc1[mi][ni][3];
            float h30 = s3v * acc3[mi][ni][0], h31 = s3v * acc3[mi][ni][1];
            float h32 = s3v * acc3[mi][ni][2], h33 = s3v * acc3[mi][ni][3];
            float g0 = siluf(h10) * h30, g1 = siluf(h11) * h31;
            float g2 = siluf(h12) * h32, g3 = siluf(h13) * h33;
            *(__half2*)(g_act + (size_t)r0 * HPAD + c)       = __floats2half2_rn(g0, g1);
            *(__half2*)(g_act + (size_t)(r0 + 8) * HPAD + c) = __floats2half2_rn(g2, g3);
        }
    }
}

// ---------------- GEMM2: out = s2 * (g . w2q^T) ----------------
// C tile 128(M) x 64(N), K=HPAD, BK=64, 3-stage pipeline, 128 threads
// (4 warps: wm in {0,1}, wn in {0,1}), 72KB smem -> 2 CTAs/SM.
// Stage layout (halves): A [0,8192) | B [8192,12288)
#define G2_STG 12288
#define G2_SMEM (3 * G2_STG * 2)

__device__ __forceinline__ void g2_load(__half* st, const __half* gA, const __half* gB,
                                        int k0, int lrow, int lch) {
#pragma unroll
    for (int i = 0; i < 8; i++) {       // A: 128 rows
        int row = lrow + (i << 4);
        int so = swz(row, lch);
        CP_ASYNC16(sptr(st + so), gA + (size_t)row * HPAD + k0 + lch * 8);
    }
#pragma unroll
    for (int i = 0; i < 4; i++) {       // B: 64 rows
        int row = lrow + (i << 4);
        int so = swz(row, lch);
        CP_ASYNC16(sptr(st + 8192 + so), gB + (size_t)row * HPAD + k0 + lch * 8);
    }
}

__global__ __launch_bounds__(128, 2) void gemm2_k(float* __restrict__ out) {
    extern __shared__ __align__(16) __half sm2[];

    const int tid = threadIdx.x, lane = tid & 31, w = tid >> 5;
    const int wm = w >> 1, wn = w & 1;
    const int bm = blockIdx.y, bn = blockIdx.x;
    const int lrow = tid >> 3, lch = tid & 7;

    const __half* gA = g_act + (size_t)bm * 128 * HPAD;
    const __half* gB = g_w2q + (size_t)bn * 64 * HPAD;

    float acc[4][4][4];
#pragma unroll
    for (int i = 0; i < 4; i++)
#pragma unroll
        for (int j = 0; j < 4; j++)
#pragma unroll
            for (int k = 0; k < 4; k++) acc[i][j][k] = 0.f;

    const int KT = HPAD / 64;  // 86

    // prologue: fill stages 0,1
#pragma unroll
    for (int s = 0; s < 2; s++) {
        g2_load(sm2 + s * G2_STG, gA, gB, s * 64, lrow, lch);
        CP_COMMIT();
    }

    int stg_w = 2, stg_r = 0;   // write/read stage indices (mod 3)
    for (int kt = 0; kt < KT; kt++) {
        CP_WAIT(1);               // stage kt landed (this thread's copies)
        __syncthreads();          // ...and everyone's copies visible
        const int nx = kt + 2;
        if (nx < KT)
            g2_load(sm2 + stg_w * G2_STG, gA, gB, nx * 64, lrow, lch);
        CP_COMMIT();
        const __half* stb = sm2 + stg_r * G2_STG;
        mma_stage_single(stb, stb + 8192, lane, wm, wn, acc);
        stg_w = (stg_w == 2) ? 0 : stg_w + 1;
        stg_r = (stg_r == 2) ? 0 : stg_r + 1;
    }

    const float s2 = g_scale[2];
    const int rb = bm * 128 + wm * 64;
    const int cb = bn * 64 + wn * 32;
#pragma unroll
    for (int mi = 0; mi < 4; mi++) {
        int r0 = rb + mi * 16 + (lane >> 2);
#pragma unroll
        for (int ni = 0; ni < 4; ni++) {
            int c = cb + ni * 8 + ((lane & 3) << 1);
            float2 v;
            v.x = s2 * acc[mi][ni][0]; v.y = s2 * acc[mi][ni][1];
            *(float2*)(out + (size_t)r0 * DM + c) = v;
            v.x = s2 * acc[mi][ni][2]; v.y = s2 * acc[mi][ni][3];
            *(float2*)(out + (size_t)(r0 + 8) * DM + c) = v;
        }
    }
}

// ---------------- launch ----------------
extern "C" void kernel_launch(void* const* d_in, const int* in_sizes, int n_in,
                              void* d_out, int out_size) {
    const float* x  = (const float*)d_in[0];
    const float* w1 = (const float*)d_in[1];
    const float* w3 = (const float*)d_in[2];
    const float* w2 = (const float*)d_in[3];
    float* out = (float*)d_out;

    const int nw = HID * DM;  // 11,184,128 (divisible by 4)

    cudaFuncSetAttribute(gemm1_k, cudaFuncAttributeMaxDynamicSharedMemorySize, G1_SMEM);
    cudaFuncSetAttribute(gemm2_k, cudaFuncAttributeMaxDynamicSharedMemorySize, G2_SMEM);

    reduce_abs3_k<<<dim3(512, 3), 256>>>(w1, w3, w2, nw / 4);             // 1
    convx_fin_k<<<MTOT * DM / 4 / 256, 256>>>(x);                         // 2
    quant_all_k<<<dim3(2, HPAD, 3), 256>>>(w1, w3, w2);                   // 3
    gemm1_k<<<dim3(HPAD / 64, MTOT / 128), 128, G1_SMEM>>>();             // 4 <- profiled
    gemm2_k<<<dim3(DM / 64, MTOT / 128), 128, G2_SMEM>>>(out);            // 5
}

// round 16
// speedup vs baseline: 1.0478x; 1.0040x over previous
#include <cuda_runtime.h>
#include <cuda_fp16.h>
#include <cstdint>

#define DM   2048
#define HID  5461
#define HPAD 5504
#define MTOT 16384

// ---------------- scratch (device globals; no allocations) ----------------
__device__ __align__(256) __half g_xh [(size_t)MTOT * DM];   // x in fp16
__device__ __align__(256) __half g_w1q[(size_t)HPAD * DM];   // ternary {-1,0,1} fp16
__device__ __align__(256) __half g_w3q[(size_t)HPAD * DM];
__device__ __align__(256) __half g_w2q[(size_t)DM * HPAD];   // [d][h] padded cols zero
__device__ __align__(256) __half g_act[(size_t)MTOT * HPAD]; // gated activation fp16
__device__ float g_partial[3 * 512];
__device__ float g_scale[3];                                  // s1, s3, s2

// ---------------- prologue kernels ----------------
__global__ void reduce_abs3_k(const float* __restrict__ w1, const float* __restrict__ w3,
                              const float* __restrict__ w2, int n4) {
    __shared__ float sd[256];
    const float* w = (blockIdx.y == 0) ? w1 : (blockIdx.y == 1) ? w3 : w2;
    const float4* w4 = (const float4*)w;
    float s = 0.f;
    for (int i = blockIdx.x * blockDim.x + threadIdx.x; i < n4; i += gridDim.x * blockDim.x) {
        float4 v = w4[i];
        s += fabsf(v.x) + fabsf(v.y) + fabsf(v.z) + fabsf(v.w);
    }
    sd[threadIdx.x] = s; __syncthreads();
    for (int st = 128; st > 0; st >>= 1) {
        if (threadIdx.x < st) sd[threadIdx.x] += sd[threadIdx.x + st];
        __syncthreads();
    }
    if (threadIdx.x == 0) g_partial[blockIdx.y * 512 + blockIdx.x] = sd[0];
}

// conv_x with finalize folded into blocks 0..2 (same pairwise tree as the old
// finalize3_k -> bitwise-identical g_scale).
__global__ void convx_fin_k(const float* __restrict__ x) {
    __shared__ float sd[256];
    if (blockIdx.x < 3) {
        const int z = blockIdx.x, tid = threadIdx.x;
        sd[tid] = g_partial[z * 512 + tid] + g_partial[z * 512 + 256 + tid];
        __syncthreads();
        for (int st = 128; st > 0; st >>= 1) {
            if (tid < st) sd[tid] += sd[tid + st];
            __syncthreads();
        }
        if (tid == 0) g_scale[z] = sd[0] / (float)(HID * DM);
    }
    int i = blockIdx.x * blockDim.x + threadIdx.x;
    const int n4 = MTOT * DM / 4;
    if (i >= n4) return;
    float4 v = ((const float4*)x)[i];
    ((__half2*)g_xh)[2 * i]     = __floats2half2_rn(v.x, v.y);
    ((__half2*)g_xh)[2 * i + 1] = __floats2half2_rn(v.z, v.w);
}

__device__ __forceinline__ float tq(float w, float s) {
    float t = rintf(w / s);                      // round-half-even, matches jnp.round
    return fmaxf(-1.f, fminf(1.f, t));
}

// Fused weight quantization. grid (2, HPAD, 3), 256 threads.
__global__ void quant_all_k(const float* __restrict__ w1, const float* __restrict__ w3,
                            const float* __restrict__ w2) {
    const int z = blockIdx.z;
    if (z < 2) {
        const float* w = z ? w3 : w1;
        __half* q = z ? g_w3q : g_w1q;
        const int r = blockIdx.y;
        const int c = (blockIdx.x * blockDim.x + threadIdx.x) << 2;
        __half2 h0, h1;
        if (r < HID) {
            const float s = g_scale[z];
            float4 v = *(const float4*)(w + (size_t)r * DM + c);
            h0 = __floats2half2_rn(tq(v.x, s), tq(v.y, s));
            h1 = __floats2half2_rn(tq(v.z, s), tq(v.w, s));
        } else {
            h0 = __floats2half2_rn(0.f, 0.f);
            h1 = h0;
        }
        uint2 pack;
        pack.x = *(unsigned*)&h0;
        pack.y = *(unsigned*)&h1;
        *(uint2*)(q + (size_t)r * DM + c) = pack;
    } else {
        const int d = blockIdx.y;
        if (d >= DM) return;
        const float s = g_scale[2];
        const float* row = w2 + (size_t)d * HID;
#pragma unroll
        for (int j = 0; j < 3; j++) {
            const int h = (blockIdx.x * blockDim.x + threadIdx.x + j * 512) << 2;
            if (h >= HPAD) break;
            float v[4];
#pragma unroll
            for (int k = 0; k < 4; k++) {
                int hk = h + k;
                v[k] = (hk < HID) ? tq(row[hk], s) : 0.f;
            }
            __half2 h0 = __floats2half2_rn(v[0], v[1]);
            __half2 h1 = __floats2half2_rn(v[2], v[3]);
            uint2 pack;
            pack.x = *(unsigned*)&h0;
            pack.y = *(unsigned*)&h1;
            *(uint2*)(g_w2q + (size_t)d * HPAD + h) = pack;
        }
    }
}

// ---------------- GEMM building blocks ----------------
#define CP_ASYNC16(s, g) asm volatile("cp.async.cg.shared.global [%0], [%1], 16;\n" :: "r"(s), "l"(g))
#define CP_COMMIT()      asm volatile("cp.async.commit_group;\n" ::)
#define CP_WAIT(N)       asm volatile("cp.async.wait_group %0;\n" :: "n"(N))

__device__ __forceinline__ unsigned sptr(const void* p) {
    return (unsigned)__cvta_generic_to_shared(p);
}

__device__ __forceinline__ void ldsm4(unsigned& r0, unsigned& r1, unsigned& r2, unsigned& r3, unsigned a) {
    asm volatile("ldmatrix.sync.aligned.m8n8.x4.shared.b16 {%0,%1,%2,%3}, [%4];\n"
                 : "=r"(r0), "=r"(r1), "=r"(r2), "=r"(r3) : "r"(a));
}

__device__ __forceinline__ void mma16816(float* c, const unsigned* a, unsigned b0, unsigned b1) {
    asm volatile(
        "mma.sync.aligned.m16n8k16.row.col.f32.f16.f16.f32 "
        "{%0,%1,%2,%3},{%4,%5,%6,%7},{%8,%9},{%0,%1,%2,%3};\n"
        : "+f"(c[0]), "+f"(c[1]), "+f"(c[2]), "+f"(c[3])
        : "r"(a[0]), "r"(a[1]), "r"(a[2]), "r"(a[3]), "r"(b0), "r"(b1));
}

// 128B-row swizzle: row = 64 halves, 8 chunks of 16B, chunk XOR (row&7). Offsets in halves.
__device__ __forceinline__ int swz(int row, int ch) {
    return (row << 6) + (((ch ^ row) & 7) << 3);
}

__device__ __forceinline__ float siluf(float x) { return x / (1.f + __expf(-x)); }

// One BK=64 panel of MMAs, dual-B (w1 and w3 share the A fragments).
// Warp tile 64(M) x 32(N); wm selects 64-row block, wn selects 32-col block.
__device__ __forceinline__ void mma_stage_dual(
    const __half* As, const __half* B1s, const __half* B3s,
    int lane, int wm, int wn, float acc1[4][4][4], float acc3[4][4][4])
{
#pragma unroll
    for (int kk = 0; kk < 4; kk++) {
        unsigned a[4][4];
#pragma unroll
        for (int mi = 0; mi < 4; mi++) {
            int row = (wm << 6) + (mi << 4) + (lane & 15);
            int ch  = (kk << 1) + (lane >> 4);
            ldsm4(a[mi][0], a[mi][1], a[mi][2], a[mi][3], sptr(As + swz(row, ch)));
        }
        unsigned b1[2][4], b3[2][4];
#pragma unroll
        for (int gi = 0; gi < 2; gi++) {
            int mat = lane >> 3;
            int row = (wn << 5) + (gi << 4) + ((mat >> 1) << 3) + (lane & 7);
            int ch  = (kk << 1) + (mat & 1);
            ldsm4(b1[gi][0], b1[gi][1], b1[gi][2], b1[gi][3], sptr(B1s + swz(row, ch)));
            ldsm4(b3[gi][0], b3[gi][1], b3[gi][2], b3[gi][3], sptr(B3s + swz(row, ch)));
        }
#pragma unroll
        for (int mi = 0; mi < 4; mi++) {
#pragma unroll
            for (int ni = 0; ni < 4; ni++) {
                int gi = ni >> 1, p = (ni & 1) << 1;
                mma16816(acc1[mi][ni], a[mi], b1[gi][p], b1[gi][p + 1]);
                mma16816(acc3[mi][ni], a[mi], b3[gi][p], b3[gi][p + 1]);
            }
        }
    }
}

// One BK=64 panel of MMAs, single B. Warp tile 64(M) x 32(N).
__device__ __forceinline__ void mma_stage_single(
    const __half* As, const __half* Bs,
    int lane, int wm, int wn, float acc[4][4][4])
{
#pragma unroll
    for (int kk = 0; kk < 4; kk++) {
        unsigned a[4][4];
#pragma unroll
        for (int mi = 0; mi < 4; mi++) {
            int row = (wm << 6) + (mi << 4) + (lane & 15);
            int ch  = (kk << 1) + (lane >> 4);
            ldsm4(a[mi][0], a[mi][1], a[mi][2], a[mi][3], sptr(As + swz(row, ch)));
        }
        unsigned b[2][4];
#pragma unroll
        for (int gi = 0; gi < 2; gi++) {
            int mat = lane >> 3;
            int row = (wn << 5) + (gi << 4) + ((mat >> 1) << 3) + (lane & 7);
            int ch  = (kk << 1) + (mat & 1);
            ldsm4(b[gi][0], b[gi][1], b[gi][2], b[gi][3], sptr(Bs + swz(row, ch)));
        }
#pragma unroll
        for (int mi = 0; mi < 4; mi++) {
#pragma unroll
            for (int ni = 0; ni < 4; ni++) {
                int gi = ni >> 1, p = (ni & 1) << 1;
                mma16816(acc[mi][ni], a[mi], b[gi][p], b[gi][p + 1]);
            }
        }
    }
}

// ---------------- GEMM1 (fused h1/h3 + SiLU gate) ----------------
// C tile 128(M) x 64(N of both h1,h3), K=2048, BK=64, 3-stage pipeline,
// 128 threads (4 warps: wm in {0,1}, wn in {0,1}), 96KB smem -> 2 CTAs/SM.
// Stage layout (halves): A [0,8192) | B1 [8192,12288) | B3 [12288,16384)
#define G1_STG 16384
#define G1_SMEM (3 * G1_STG * 2)
#define EROW 72   // epilogue smem row pitch in halves (144B, conflict-free)

__device__ __forceinline__ void g1_load(__half* st, const __half* gA, const __half* gB1,
                                        const __half* gB3, int k0, int lrow, int lch) {
#pragma unroll
    for (int i = 0; i < 8; i++) {       // A: 128 rows
        int row = lrow + (i << 4);
        int so = swz(row, lch);
        CP_ASYNC16(sptr(st + so), gA + (size_t)row * DM + k0 + lch * 8);
    }
#pragma unroll
    for (int i = 0; i < 4; i++) {       // B1/B3: 64 rows each
        int row = lrow + (i << 4);
        int so = swz(row, lch);
        size_t go = (size_t)row * DM + k0 + lch * 8;
        CP_ASYNC16(sptr(st + 8192 + so),  gB1 + go);
        CP_ASYNC16(sptr(st + 12288 + so), gB3 + go);
    }
}

__global__ __launch_bounds__(128, 2) void gemm1_k() {
    extern __shared__ __align__(16) __half sm1[];

    const int tid = threadIdx.x, lane = tid & 31, w = tid >> 5;
    const int wm = w >> 1, wn = w & 1;
    const int bm = blockIdx.y, bn = blockIdx.x;
    const int lrow = tid >> 3, lch = tid & 7;   // 16 rows per pass, 8 chunks/row

    const __half* gA  = g_xh  + (size_t)bm * 128 * DM;
    const __half* gB1 = g_w1q + (size_t)bn * 64 * DM;
    const __half* gB3 = g_w3q + (size_t)bn * 64 * DM;

    float acc1[4][4][4], acc3[4][4][4];
#pragma unroll
    for (int i = 0; i < 4; i++)
#pragma unroll
        for (int j = 0; j < 4; j++)
#pragma unroll
            for (int k = 0; k < 4; k++) { acc1[i][j][k] = 0.f; acc3[i][j][k] = 0.f; }

    const int KT = DM / 64;  // 32

    // prologue: fill stages 0,1
#pragma unroll
    for (int s = 0; s < 2; s++) {
        g1_load(sm1 + s * G1_STG, gA, gB1, gB3, s * 64, lrow, lch);
        CP_COMMIT();
    }

    int stg_w = 2, stg_r = 0;   // write/read stage indices (mod 3)
    for (int kt = 0; kt < KT; kt++) {
        CP_WAIT(1);               // stage kt landed (this thread's copies)
        __syncthreads();          // ...and everyone's copies visible
        const int nx = kt + 2;
        if (nx < KT)
            g1_load(sm1 + stg_w * G1_STG, gA, gB1, gB3, nx * 64, lrow, lch);
        CP_COMMIT();
        const __half* stb = sm1 + stg_r * G1_STG;
        mma_stage_dual(stb, stb + 8192, stb + 12288, lane, wm, wn, acc1, acc3);
        stg_w = (stg_w == 2) ? 0 : stg_w + 1;
        stg_r = (stg_r == 2) ? 0 : stg_r + 1;
    }

    // epilogue: g = silu(s1*h1) * (s3*h3), staged through smem for coalesced
    // 128B-row stores (direct per-lane half2 stores waste half of each sector).
    const float s1 = g_scale[0], s3v = g_scale[1];
    __syncthreads();              // all warps done reading pipeline buffers
#pragma unroll
    for (int mi = 0; mi < 4; mi++) {
        int lr = (wm << 6) + mi * 16 + (lane >> 2);
#pragma unroll
        for (int ni = 0; ni < 4; ni++) {
            int lc = (wn << 5) + ni * 8 + ((lane & 3) << 1);
            float h10 = s1 * acc1[mi][ni][0], h11 = s1 * acc1[mi][ni][1];
            float h12 = s1 * acc1[mi][ni][2], h13 = s1 * acc1[mi][ni][3];
            float h30 = s3v * acc3[mi][ni][0], h31 = s3v * acc3[mi][ni][1];
            float h32 = s3v * acc3[mi][ni][2], h33 = s3v * acc3[mi][ni][3];
            *(__half2*)(sm1 + lr * EROW + lc) =
                __floats2half2_rn(siluf(h10) * h30, siluf(h11) * h31);
            *(__half2*)(sm1 + (lr + 8) * EROW + lc) =
                __floats2half2_rn(siluf(h12) * h32, siluf(h13) * h33);
        }
    }
    __syncthreads();
    {
        const float4* src = (const float4*)(sm1 + tid * EROW);
        float4* dst = (float4*)(g_act + (size_t)(bm * 128 + tid) * HPAD + bn * 64);
#pragma unroll
        for (int j = 0; j < 8; j++) dst[j] = src[j];
    }
}

// ---------------- GEMM2: out = s2 * (g . w2q^T) ----------------
// C tile 128(M) x 64(N), K=HPAD, BK=64, 3-stage pipeline, 128 threads
// (4 warps: wm in {0,1}, wn in {0,1}), 72KB smem -> 2 CTAs/SM.
// Stage layout (halves): A [0,8192) | B [8192,12288)
#define G2_STG 12288
#define G2_SMEM (3 * G2_STG * 2)

__device__ __forceinline__ void g2_load(__half* st, const __half* gA, const __half* gB,
                                        int k0, int lrow, int lch) {
#pragma unroll
    for (int i = 0; i < 8; i++) {       // A: 128 rows
        int row = lrow + (i << 4);
        int so = swz(row, lch);
        CP_ASYNC16(sptr(st + so), gA + (size_t)row * HPAD + k0 + lch * 8);
    }
#pragma unroll
    for (int i = 0; i < 4; i++) {       // B: 64 rows
        int row = lrow + (i << 4);
        int so = swz(row, lch);
        CP_ASYNC16(sptr(st + 8192 + so), gB + (size_t)row * HPAD + k0 + lch * 8);
    }
}

__global__ __launch_bounds__(128, 2) void gemm2_k(float* __restrict__ out) {
    extern __shared__ __align__(16) __half sm2[];

    const int tid = threadIdx.x, lane = tid & 31, w = tid >> 5;
    const int wm = w >> 1, wn = w & 1;
    const int bm = blockIdx.y, bn = blockIdx.x;
    const int lrow = tid >> 3, lch = tid & 7;

    const __half* gA = g_act + (size_t)bm * 128 * HPAD;
    const __half* gB = g_w2q + (size_t)bn * 64 * HPAD;

    float acc[4][4][4];
#pragma unroll
    for (int i = 0; i < 4; i++)
#pragma unroll
        for (int j = 0; j < 4; j++)
#pragma unroll
            for (int k = 0; k < 4; k++) acc[i][j][k] = 0.f;

    const int KT = HPAD / 64;  // 86

    // prologue: fill stages 0,1
#pragma unroll
    for (int s = 0; s < 2; s++) {
        g2_load(sm2 + s * G2_STG, gA, gB, s * 64, lrow, lch);
        CP_COMMIT();
    }

    int stg_w = 2, stg_r = 0;   // write/read stage indices (mod 3)
    for (int kt = 0; kt < KT; kt++) {
        CP_WAIT(1);               // stage kt landed (this thread's copies)
        __syncthreads();          // ...and everyone's copies visible
        const int nx = kt + 2;
        if (nx < KT)
            g2_load(sm2 + stg_w * G2_STG, gA, gB, nx * 64, lrow, lch);
        CP_COMMIT();
        const __half* stb = sm2 + stg_r * G2_STG;
        mma_stage_single(stb, stb + 8192, lane, wm, wn, acc);
        stg_w = (stg_w == 2) ? 0 : stg_w + 1;
        stg_r = (stg_r == 2) ? 0 : stg_r + 1;
    }

    const float s2 = g_scale[2];
    const int rb = bm * 128 + wm * 64;
    const int cb = bn * 64 + wn * 32;
#pragma unroll
    for (int mi = 0; mi < 4; mi++) {
        int r0 = rb + mi * 16 + (lane >> 2);
#pragma unroll
        for (int ni = 0; ni < 4; ni++) {
            int c = cb + ni * 8 + ((lane & 3) << 1);
            float2 v;
            v.x = s2 * acc[mi][ni][0]; v.y = s2 * acc[mi][ni][1];
            *(float2*)(out + (size_t)r0 * DM + c) = v;
            v.x = s2 * acc[mi][ni][2]; v.y = s2 * acc[mi][ni][3];
            *(float2*)(out + (size_t)(r0 + 8) * DM + c) = v;
        }
    }
}

// ---------------- launch ----------------
extern "C" void kernel_launch(void* const* d_in, const int* in_sizes, int n_in,
                              void* d_out, int out_size) {
    const float* x  = (const float*)d_in[0];
    const float* w1 = (const float*)d_in[1];
    const float* w3 = (const float*)d_in[2];
    const float* w2 = (const float*)d_in[3];
    float* out = (float*)d_out;

    const int nw = HID * DM;  // 11,184,128 (divisible by 4)

    cudaFuncSetAttribute(gemm1_k, cudaFuncAttributeMaxDynamicSharedMemorySize, G1_SMEM);
    cudaFuncSetAttribute(gemm2_k, cudaFuncAttributeMaxDynamicSharedMemorySize, G2_SMEM);

    reduce_abs3_k<<<dim3(512, 3), 256>>>(w1, w3, w2, nw / 4);             // 1
    convx_fin_k<<<MTOT * DM / 4 / 256, 256>>>(x);                         // 2
    quant_all_k<<<dim3(2, HPAD, 3), 256>>>(w1, w3, w2);                   // 3
    gemm1_k<<<dim3(HPAD / 64, MTOT / 128), 128, G1_SMEM>>>();             // 4 <- profiled
    gemm2_k<<<dim3(DM / 64, MTOT / 128), 128, G2_SMEM>>>(out);            // 5
}